// round 7
// baseline (speedup 1.0000x reference)
#include <cuda_runtime.h>

#define NUM_NODE 150
#define FEAT 4
#define ROWF (NUM_NODE * FEAT)   // 600 floats per row
#define THREADS 1024             // 32 warps/block -> 64 contiguous rows per block

// streaming float2 load with 256B L2 prefetch (sequential row stream)
static __device__ __forceinline__ float2 ldcs256(const float* p) {
    float2 v;
    asm volatile("ld.global.cs.L2::256B.v2.f32 {%0,%1}, [%2];"
                 : "=f"(v.x), "=f"(v.y) : "l"(p));
    return v;
}
// streaming store (evict-first in L2)
static __device__ __forceinline__ void stcs2(float* p, float x, float y) {
    asm volatile("st.global.cs.v2.f32 [%0], {%1,%2};" :: "l"(p), "f"(x), "f"(y) : "memory");
}

__global__ __launch_bounds__(THREADS)
void obstacle_lane_kernel(const float* __restrict__ lf,
                          const float2* __restrict__ obs_pos,
                          const int* __restrict__ mask,
                          float* __restrict__ out,
                          int M)
{
    int warp = (blockIdx.x * blockDim.x + threadIdx.x) >> 5;
    int lane = threadIdx.x & 31;

    int r0 = 2 * warp;
    if (r0 >= M) return;
    int r1 = r0 + 1;
    if (r1 >= M) r1 = r0;           // duplicate (benign: identical writes)

    const float* row0 = lf + (long)r0 * ROWF;
    const float* row1 = lf + (long)r1 * ROWF;

    // rep = obs_pos[mask[r]]  (mask is sorted -> heavy cache reuse)
    float2 rp0 = __ldg(obs_pos + __ldg(mask + r0));
    float2 rp1 = __ldg(obs_pos + __ldg(mask + r1));

    // node indices for this lane: 1+lane, 33+lane, 65+lane, 97+lane, min(129+lane,148)
    int i4 = min(129 + lane, 148);
    int o0 = 4 * (1 + lane);
    int o4 = 4 * i4;

    // ---- front-batched: 10 independent streaming loads in flight ----
    float2 a0 = ldcs256(row0 + o0);
    float2 a1 = ldcs256(row0 + o0 + 128);
    float2 a2 = ldcs256(row0 + o0 + 256);
    float2 a3 = ldcs256(row0 + o0 + 384);
    float2 a4 = ldcs256(row0 + o4);
    float2 b0 = ldcs256(row1 + o0);
    float2 b1 = ldcs256(row1 + o0 + 128);
    float2 b2 = ldcs256(row1 + o0 + 256);
    float2 b3 = ldcs256(row1 + o0 + 384);
    float2 b4 = ldcs256(row1 + o4);

    // ---- two interleaved argmin chains ----
    float best0, best1;
    int   bidx0, bidx1;
    {
        float dx, dy, d;
        dx = a0.x - rp0.x; dy = a0.y - rp0.y; best0 = dx*dx + dy*dy; bidx0 = 1 + lane;
        dx = b0.x - rp1.x; dy = b0.y - rp1.y; best1 = dx*dx + dy*dy; bidx1 = 1 + lane;

        dx = a1.x - rp0.x; dy = a1.y - rp0.y; d = dx*dx + dy*dy;
        if (d < best0) { best0 = d; bidx0 = 33 + lane; }
        dx = b1.x - rp1.x; dy = b1.y - rp1.y; d = dx*dx + dy*dy;
        if (d < best1) { best1 = d; bidx1 = 33 + lane; }

        dx = a2.x - rp0.x; dy = a2.y - rp0.y; d = dx*dx + dy*dy;
        if (d < best0) { best0 = d; bidx0 = 65 + lane; }
        dx = b2.x - rp1.x; dy = b2.y - rp1.y; d = dx*dx + dy*dy;
        if (d < best1) { best1 = d; bidx1 = 65 + lane; }

        dx = a3.x - rp0.x; dy = a3.y - rp0.y; d = dx*dx + dy*dy;
        if (d < best0) { best0 = d; bidx0 = 97 + lane; }
        dx = b3.x - rp1.x; dy = b3.y - rp1.y; d = dx*dx + dy*dy;
        if (d < best1) { best1 = d; bidx1 = 97 + lane; }

        dx = a4.x - rp0.x; dy = a4.y - rp0.y; d = dx*dx + dy*dy;
        if (d < best0) { best0 = d; bidx0 = i4; }
        dx = b4.x - rp1.x; dy = b4.y - rp1.y; d = dx*dx + dy*dy;
        if (d < best1) { best1 = d; bidx1 = i4; }
    }

    // ---- butterfly min (both rows overlapped), then min-index among minima ----
    float m0 = best0, m1 = best1;
#pragma unroll
    for (int off = 16; off > 0; off >>= 1) {
        m0 = fminf(m0, __shfl_xor_sync(0xffffffffu, m0, off));
        m1 = fminf(m1, __shfl_xor_sync(0xffffffffu, m1, off));
    }
    unsigned c0 = (best0 == m0) ? (unsigned)bidx0 : 0x7fffffffu;
    unsigned c1 = (best1 == m1) ? (unsigned)bidx1 : 0x7fffffffu;
    int gi0 = (int)__reduce_min_sync(0xffffffffu, c0);
    int gi1 = (int)__reduce_min_sync(0xffffffffu, c1);

    // ---- epilogues for both rows run concurrently on lanes 0 and 1 ----
    if (lane < 2) {
        int    r   = (lane == 0) ? r0  : r1;
        int    bi  = (lane == 0) ? gi0 : gi1;
        float2 rp  = (lane == 0) ? rp0 : rp1;
        const float* row = (lane == 0) ? row0 : row1;

        float4 mn = *reinterpret_cast<const float4*>(row + 4 * bi);
        float4 pv = *reinterpret_cast<const float4*>(row + 4 * (bi - 1));
        float4 nx = *reinterpret_cast<const float4*>(row + 4 * (bi + 1));

        float dpx = pv.x - mn.x, dpy = pv.y - mn.y, dpz = pv.z - mn.z, dpw = pv.w - mn.w;
        float dnx = nx.x - mn.x, dny = nx.y - mn.y, dnz = nx.z - mn.z, dnw = nx.w - mn.w;
        float dist_prev = dpx*dpx + dpy*dpy + dpz*dpz + dpw*dpw;
        float dist_next = dnx*dnx + dny*dny + dnz*dnz + dnw*dnw;

        int before, after;
        float sx, sy, ex, ey;
        if (dist_next < dist_prev) {
            before = bi;     after = bi + 1;
            sx = mn.x; sy = mn.y; ex = nx.x; ey = nx.y;
        } else {
            before = bi - 1; after = bi;
            sx = pv.x; sy = pv.y; ex = mn.x; ey = mn.y;
        }

        float lvx = ex - sx, lvy = ey - sy;
        float mag = sqrtf(lvx * lvx + lvy * lvy);
        float ux = lvx / mag, uy = lvy / mag;
        float pm = (rp.x - sx) * ux + (rp.y - sy) * uy;

        // output layout: [proj_pt (M,2) | indices (M,2) | rep (M,2)] flattened f32
        long o1 = 2L * M;
        long o2 = 4L * M;
        stcs2(out + 2 * r,      sx + pm * ux,  sy + pm * uy);
        stcs2(out + o1 + 2 * r, (float)before, (float)after);
        stcs2(out + o2 + 2 * r, rp.x,          rp.y);
    }
}

extern "C" void kernel_launch(void* const* d_in, const int* in_sizes, int n_in,
                              void* d_out, int out_size)
{
    const float*  lf      = (const float*)d_in[0];   // (M, 150, 4) f32
    const float2* obs_pos = (const float2*)d_in[1];  // (N, 2) f32
    const int*    mask    = (const int*)d_in[2];     // (M, 1) i32
    float* out = (float*)d_out;

    int M = in_sizes[0] / ROWF;

    // 32 warps/block, 2 rows/warp = 64 contiguous rows (153.6 KB) per block:
    // ~4x fewer concurrent DRAM streams chip-wide -> better row-buffer locality
    int warps_needed = (M + 1) / 2;
    int blocks = (warps_needed + 31) / 32;
    obstacle_lane_kernel<<<blocks, THREADS>>>(lf, obs_pos, mask, out, M);
}

// round 8
// speedup vs baseline: 1.0550x; 1.0550x over previous
#include <cuda_runtime.h>

#define NUM_NODE 150
#define FEAT 4
#define ROWF (NUM_NODE * FEAT)   // 600 floats per row

__global__ __launch_bounds__(256)
void obstacle_lane_kernel(const float* __restrict__ lf,
                          const float2* __restrict__ obs_pos,
                          const int* __restrict__ mask,
                          float* __restrict__ out,
                          int M)
{
    int warp = (blockIdx.x * blockDim.x + threadIdx.x) >> 5;
    int lane = threadIdx.x & 31;

    int r0 = 2 * warp;
    if (r0 >= M) return;
    int r1 = r0 + 1;
    if (r1 >= M) r1 = r0;           // duplicate (benign: identical writes)

    const float* row0 = lf + (long)r0 * ROWF;
    const float* row1 = lf + (long)r1 * ROWF;

    // rep = obs_pos[mask[r]]  (mask is sorted -> heavy cache reuse)
    float2 rp0 = __ldg(obs_pos + __ldg(mask + r0));
    float2 rp1 = __ldg(obs_pos + __ldg(mask + r1));

    // node indices for this lane: 1+lane, 33+lane, 65+lane, 97+lane, min(129+lane,148)
    int i4 = min(129 + lane, 148);
    int o0 = 4 * (1 + lane);
    int o4 = 4 * i4;

    // ---- front-batched: 10 independent streaming loads in flight ----
    float2 a0 = __ldcs((const float2*)(row0 + o0));
    float2 a1 = __ldcs((const float2*)(row0 + o0 + 128));
    float2 a2 = __ldcs((const float2*)(row0 + o0 + 256));
    float2 a3 = __ldcs((const float2*)(row0 + o0 + 384));
    float2 a4 = __ldcs((const float2*)(row0 + o4));
    float2 b0 = __ldcs((const float2*)(row1 + o0));
    float2 b1 = __ldcs((const float2*)(row1 + o0 + 128));
    float2 b2 = __ldcs((const float2*)(row1 + o0 + 256));
    float2 b3 = __ldcs((const float2*)(row1 + o0 + 384));
    float2 b4 = __ldcs((const float2*)(row1 + o4));

    // ---- two interleaved argmin chains ----
    float best0, best1;
    int   bidx0, bidx1;
    {
        float dx, dy, d;
        dx = a0.x - rp0.x; dy = a0.y - rp0.y; best0 = dx*dx + dy*dy; bidx0 = 1 + lane;
        dx = b0.x - rp1.x; dy = b0.y - rp1.y; best1 = dx*dx + dy*dy; bidx1 = 1 + lane;

        dx = a1.x - rp0.x; dy = a1.y - rp0.y; d = dx*dx + dy*dy;
        if (d < best0) { best0 = d; bidx0 = 33 + lane; }
        dx = b1.x - rp1.x; dy = b1.y - rp1.y; d = dx*dx + dy*dy;
        if (d < best1) { best1 = d; bidx1 = 33 + lane; }

        dx = a2.x - rp0.x; dy = a2.y - rp0.y; d = dx*dx + dy*dy;
        if (d < best0) { best0 = d; bidx0 = 65 + lane; }
        dx = b2.x - rp1.x; dy = b2.y - rp1.y; d = dx*dx + dy*dy;
        if (d < best1) { best1 = d; bidx1 = 65 + lane; }

        dx = a3.x - rp0.x; dy = a3.y - rp0.y; d = dx*dx + dy*dy;
        if (d < best0) { best0 = d; bidx0 = 97 + lane; }
        dx = b3.x - rp1.x; dy = b3.y - rp1.y; d = dx*dx + dy*dy;
        if (d < best1) { best1 = d; bidx1 = 97 + lane; }

        dx = a4.x - rp0.x; dy = a4.y - rp0.y; d = dx*dx + dy*dy;
        if (d < best0) { best0 = d; bidx0 = i4; }
        dx = b4.x - rp1.x; dy = b4.y - rp1.y; d = dx*dx + dy*dy;
        if (d < best1) { best1 = d; bidx1 = i4; }
    }

    // ---- butterfly min (both rows overlapped), then min-index among minima ----
    float m0 = best0, m1 = best1;
#pragma unroll
    for (int off = 16; off > 0; off >>= 1) {
        m0 = fminf(m0, __shfl_xor_sync(0xffffffffu, m0, off));
        m1 = fminf(m1, __shfl_xor_sync(0xffffffffu, m1, off));
    }
    unsigned c0 = (best0 == m0) ? (unsigned)bidx0 : 0x7fffffffu;
    unsigned c1 = (best1 == m1) ? (unsigned)bidx1 : 0x7fffffffu;
    int gi0 = (int)__reduce_min_sync(0xffffffffu, c0);
    int gi1 = (int)__reduce_min_sync(0xffffffffu, c1);

    // ---- epilogues for both rows run concurrently on lanes 0 and 1 ----
    if (lane < 2) {
        int    r   = (lane == 0) ? r0  : r1;
        int    bi  = (lane == 0) ? gi0 : gi1;
        float2 rp  = (lane == 0) ? rp0 : rp1;
        const float* row = (lane == 0) ? row0 : row1;

        float4 mn = __ldg(reinterpret_cast<const float4*>(row + 4 * bi));
        float4 pv = __ldg(reinterpret_cast<const float4*>(row + 4 * (bi - 1)));
        float4 nx = __ldg(reinterpret_cast<const float4*>(row + 4 * (bi + 1)));

        float dpx = pv.x - mn.x, dpy = pv.y - mn.y, dpz = pv.z - mn.z, dpw = pv.w - mn.w;
        float dnx = nx.x - mn.x, dny = nx.y - mn.y, dnz = nx.z - mn.z, dnw = nx.w - mn.w;
        float dist_prev = dpx*dpx + dpy*dpy + dpz*dpz + dpw*dpw;
        float dist_next = dnx*dnx + dny*dny + dnz*dnz + dnw*dnw;

        int before, after;
        float sx, sy, ex, ey;
        if (dist_next < dist_prev) {
            before = bi;     after = bi + 1;
            sx = mn.x; sy = mn.y; ex = nx.x; ey = nx.y;
        } else {
            before = bi - 1; after = bi;
            sx = pv.x; sy = pv.y; ex = mn.x; ey = mn.y;
        }

        float lvx = ex - sx, lvy = ey - sy;
        float mag = sqrtf(lvx * lvx + lvy * lvy);
        float ux = lvx / mag, uy = lvy / mag;
        float pm = (rp.x - sx) * ux + (rp.y - sy) * uy;

        // output layout: [proj_pt (M,2) | indices (M,2) | rep (M,2)] flattened f32
        long o1 = 2L * M;
        long o2 = 4L * M;
        out[2 * r + 0]      = sx + pm * ux;
        out[2 * r + 1]      = sy + pm * uy;
        out[o1 + 2 * r + 0] = (float)before;
        out[o1 + 2 * r + 1] = (float)after;
        out[o2 + 2 * r + 0] = rp.x;
        out[o2 + 2 * r + 1] = rp.y;
    }
}

extern "C" void kernel_launch(void* const* d_in, const int* in_sizes, int n_in,
                              void* d_out, int out_size)
{
    const float*  lf      = (const float*)d_in[0];   // (M, 150, 4) f32
    const float2* obs_pos = (const float2*)d_in[1];  // (N, 2) f32
    const int*    mask    = (const int*)d_in[2];     // (M, 1) i32
    float* out = (float*)d_out;

    int M = in_sizes[0] / ROWF;

    const int threads = 256;               // 8 warps/block, 2 rows/warp = 16 rows/block
    int warps_needed = (M + 1) / 2;
    int blocks = (warps_needed + 7) / 8;
    obstacle_lane_kernel<<<blocks, threads>>>(lf, obs_pos, mask, out, M);
}